// round 1
// baseline (speedup 1.0000x reference)
#include <cuda_runtime.h>

// Problem constants
#define NBT   96      // B*T = 8*12
#define NSEQ  512     // N
#define DMODEL 64     // D
#define KH    8       // heads
#define HD    8       // per-head dim
#define TOKENS (NBT * NSEQ)   // 49152

// Scratch (head-major q/k/v: [h][bt][n][d]) and attention output ([tok][64])
__device__ float g_q[KH * NBT * NSEQ * HD];
__device__ float g_k[KH * NBT * NSEQ * HD];
__device__ float g_v[KH * NBT * NSEQ * HD];
__device__ float g_att[TOKENS * DMODEL];

// ---------------------------------------------------------------------------
// Fast exp on the FMA pipe (avoids MUFU bottleneck).
// exp(x) = 2^r * e^g,  r = rint(x*log2e), g = x - r*ln2, |g| <= 0.347
// ---------------------------------------------------------------------------
__device__ __forceinline__ float fexp(float x) {
    // t = x*log2e + magic  (single fma; low mantissa bits of t hold rint as int)
    float t = __fmaf_rn(x, 1.4426950408889634f, 12582912.0f);
    unsigned ni = (unsigned)__float_as_int(t);
    float r = __fadd_rn(t, -12582912.0f);        // r = rint(x*log2e)
    // g = x - r*ln2  (hi/lo split for accuracy)
    float g = __fmaf_rn(r, -0.693145751953125f, x);
    g = __fmaf_rn(r, -1.428606765330187e-06f, g);
    // e^g, Cephes degree-5
    float p = 1.9875691500e-4f;
    p = __fmaf_rn(p, g, 1.3981999507e-3f);
    p = __fmaf_rn(p, g, 8.3334519073e-3f);
    p = __fmaf_rn(p, g, 4.1665795894e-2f);
    p = __fmaf_rn(p, g, 1.6666665459e-1f);
    p = __fmaf_rn(p, g, 5.0000001201e-1f);
    float eg = __fmaf_rn(g * g, p, g) + 1.0f;
    // scale = 2^r via bit trick: (ni<<23) == (int)r << 23
    float s = __uint_as_float((ni << 23) + 0x3f800000u);
    return eg * s;
}

// ---------------------------------------------------------------------------
// Kernel 1: fused QKV projection.
// H = [X | STE] (49152 x 128);  out_mat = relu(H @ W + b), written head-major.
// grid (768, 3): blockIdx.x = 64-row tile, blockIdx.y = matrix (q/k/v).
// ---------------------------------------------------------------------------
__global__ __launch_bounds__(256) void qkv_kernel(
    const float* __restrict__ X, const float* __restrict__ STE,
    const float* __restrict__ W7, const float* __restrict__ b7,
    const float* __restrict__ W8, const float* __restrict__ b8,
    const float* __restrict__ W9, const float* __restrict__ b9)
{
    __shared__ float sA[64][33];   // [row][k] padded
    __shared__ float sB[32][64];   // [k][col]

    const int mat = blockIdx.y;
    const float* W  = (mat == 0) ? W7 : (mat == 1) ? W8 : W9;
    const float* bv = (mat == 0) ? b7 : (mat == 1) ? b8 : b9;
    float* gout     = (mat == 0) ? g_q : (mat == 1) ? g_k : g_v;

    const int row0 = blockIdx.x * 64;
    const int tid  = threadIdx.x;
    const int tx   = tid & 15;     // col group (4 cols each)
    const int ty   = tid >> 4;     // row group (4 rows each)

    float c[4][4];
    #pragma unroll
    for (int i = 0; i < 4; i++)
        #pragma unroll
        for (int j = 0; j < 4; j++) c[i][j] = 0.0f;

    #pragma unroll 1
    for (int kc = 0; kc < 4; kc++) {
        const float* src = (kc < 2) ? X : STE;
        const int kbase = (kc & 1) * 32;       // within X/STE's 64 cols
        const int kglob = kc * 32;             // within H's 128 cols

        // Load A tile: 64 rows x 32 k (coalesced over k)
        #pragma unroll
        for (int e = 0; e < 8; e++) {
            int idx = e * 256 + tid;
            int rr = idx >> 5, kk = idx & 31;
            sA[rr][kk] = src[(row0 + rr) * 64 + kbase + kk];
        }
        // Load B tile: 32 k x 64 cols (coalesced over cols)
        #pragma unroll
        for (int e = 0; e < 8; e++) {
            int idx = e * 256 + tid;
            int kk = idx >> 6, j = idx & 63;
            sB[kk][j] = W[(kglob + kk) * 64 + j];
        }
        __syncthreads();

        #pragma unroll
        for (int kk = 0; kk < 32; kk++) {
            float a0 = sA[ty * 4 + 0][kk];
            float a1 = sA[ty * 4 + 1][kk];
            float a2 = sA[ty * 4 + 2][kk];
            float a3 = sA[ty * 4 + 3][kk];
            float4 b = *(const float4*)&sB[kk][tx * 4];
            c[0][0] = __fmaf_rn(a0, b.x, c[0][0]);
            c[0][1] = __fmaf_rn(a0, b.y, c[0][1]);
            c[0][2] = __fmaf_rn(a0, b.z, c[0][2]);
            c[0][3] = __fmaf_rn(a0, b.w, c[0][3]);
            c[1][0] = __fmaf_rn(a1, b.x, c[1][0]);
            c[1][1] = __fmaf_rn(a1, b.y, c[1][1]);
            c[1][2] = __fmaf_rn(a1, b.z, c[1][2]);
            c[1][3] = __fmaf_rn(a1, b.w, c[1][3]);
            c[2][0] = __fmaf_rn(a2, b.x, c[2][0]);
            c[2][1] = __fmaf_rn(a2, b.y, c[2][1]);
            c[2][2] = __fmaf_rn(a2, b.z, c[2][2]);
            c[2][3] = __fmaf_rn(a2, b.w, c[2][3]);
            c[3][0] = __fmaf_rn(a3, b.x, c[3][0]);
            c[3][1] = __fmaf_rn(a3, b.y, c[3][1]);
            c[3][2] = __fmaf_rn(a3, b.z, c[3][2]);
            c[3][3] = __fmaf_rn(a3, b.w, c[3][3]);
        }
        __syncthreads();
    }

    // Epilogue: relu(+bias), scatter to head-major layout
    const int w  = tx * 4;          // col in [0,64): stays within one head (8|4)
    const int h  = w >> 3;
    const int dd = w & 7;           // 0 or 4 -> float4-aligned
    float4 bb = *(const float4*)&bv[w];
    #pragma unroll
    for (int i = 0; i < 4; i++) {
        int tok = row0 + ty * 4 + i;
        int bt = tok >> 9, n = tok & 511;
        float4 o;
        o.x = fmaxf(c[i][0] + bb.x, 0.0f);
        o.y = fmaxf(c[i][1] + bb.y, 0.0f);
        o.z = fmaxf(c[i][2] + bb.z, 0.0f);
        o.w = fmaxf(c[i][3] + bb.w, 0.0f);
        *(float4*)&gout[(((h * NBT) + bt) * NSEQ + n) * HD + dd] = o;
    }
}

// ---------------------------------------------------------------------------
// Kernel 2: attention per (bt, head). K,V resident in smem; single-pass
// softmax (scores >= 0 and bounded, no max subtraction needed in fp32).
// grid (96, 8), 256 threads, 2 queries/thread.
// ---------------------------------------------------------------------------
__global__ __launch_bounds__(256) void attn_kernel()
{
    __shared__ float4 sk[NSEQ * 2];   // k[j] as 2 float4
    __shared__ float4 sv[NSEQ * 2];

    const int bt = blockIdx.x;
    const int h  = blockIdx.y;
    const int tid = threadIdx.x;
    const int base = ((h * NBT + bt) * NSEQ) * HD;   // float offset

    const float4* gk4 = (const float4*)(g_k + base);
    const float4* gv4 = (const float4*)(g_v + base);
    const float4* gq4 = (const float4*)(g_q + base);

    #pragma unroll
    for (int e = 0; e < 4; e++) {
        sk[e * 256 + tid] = gk4[e * 256 + tid];
        sv[e * 256 + tid] = gv4[e * 256 + tid];
    }

    const float scale = 0.35355339059327373f;   // 1/sqrt(8)
    float q0[8], q1[8];
    {
        float4 a = gq4[tid * 2], b = gq4[tid * 2 + 1];
        q0[0] = a.x * scale; q0[1] = a.y * scale; q0[2] = a.z * scale; q0[3] = a.w * scale;
        q0[4] = b.x * scale; q0[5] = b.y * scale; q0[6] = b.z * scale; q0[7] = b.w * scale;
        float4 cc = gq4[(tid + 256) * 2], d = gq4[(tid + 256) * 2 + 1];
        q1[0] = cc.x * scale; q1[1] = cc.y * scale; q1[2] = cc.z * scale; q1[3] = cc.w * scale;
        q1[4] = d.x * scale; q1[5] = d.y * scale; q1[6] = d.z * scale; q1[7] = d.w * scale;
    }
    __syncthreads();

    float acc0[8], acc1[8];
    #pragma unroll
    for (int i = 0; i < 8; i++) { acc0[i] = 0.0f; acc1[i] = 0.0f; }
    float l0 = 0.0f, l1 = 0.0f;

    #pragma unroll 2
    for (int j = 0; j < NSEQ; j++) {
        float4 ka = sk[j * 2], kb = sk[j * 2 + 1];

        float s0 = q0[0] * ka.x;
        s0 = __fmaf_rn(q0[1], ka.y, s0);
        s0 = __fmaf_rn(q0[2], ka.z, s0);
        s0 = __fmaf_rn(q0[3], ka.w, s0);
        s0 = __fmaf_rn(q0[4], kb.x, s0);
        s0 = __fmaf_rn(q0[5], kb.y, s0);
        s0 = __fmaf_rn(q0[6], kb.z, s0);
        s0 = __fmaf_rn(q0[7], kb.w, s0);

        float s1 = q1[0] * ka.x;
        s1 = __fmaf_rn(q1[1], ka.y, s1);
        s1 = __fmaf_rn(q1[2], ka.z, s1);
        s1 = __fmaf_rn(q1[3], ka.w, s1);
        s1 = __fmaf_rn(q1[4], kb.x, s1);
        s1 = __fmaf_rn(q1[5], kb.y, s1);
        s1 = __fmaf_rn(q1[6], kb.z, s1);
        s1 = __fmaf_rn(q1[7], kb.w, s1);

        float p0 = fexp(s0);
        float p1 = fexp(s1);
        l0 += p0;
        l1 += p1;

        float4 va = sv[j * 2], vb = sv[j * 2 + 1];
        acc0[0] = __fmaf_rn(p0, va.x, acc0[0]);
        acc0[1] = __fmaf_rn(p0, va.y, acc0[1]);
        acc0[2] = __fmaf_rn(p0, va.z, acc0[2]);
        acc0[3] = __fmaf_rn(p0, va.w, acc0[3]);
        acc0[4] = __fmaf_rn(p0, vb.x, acc0[4]);
        acc0[5] = __fmaf_rn(p0, vb.y, acc0[5]);
        acc0[6] = __fmaf_rn(p0, vb.z, acc0[6]);
        acc0[7] = __fmaf_rn(p0, vb.w, acc0[7]);
        acc1[0] = __fmaf_rn(p1, va.x, acc1[0]);
        acc1[1] = __fmaf_rn(p1, va.y, acc1[1]);
        acc1[2] = __fmaf_rn(p1, va.z, acc1[2]);
        acc1[3] = __fmaf_rn(p1, va.w, acc1[3]);
        acc1[4] = __fmaf_rn(p1, vb.x, acc1[4]);
        acc1[5] = __fmaf_rn(p1, vb.y, acc1[5]);
        acc1[6] = __fmaf_rn(p1, vb.z, acc1[6]);
        acc1[7] = __fmaf_rn(p1, vb.w, acc1[7]);
    }

    float r0 = 1.0f / l0;
    float r1 = 1.0f / l1;

    // write to token-major [tok][64] at head column h*8
    {
        int tok = bt * NSEQ + tid;
        float4 o;
        o.x = acc0[0] * r0; o.y = acc0[1] * r0; o.z = acc0[2] * r0; o.w = acc0[3] * r0;
        *(float4*)&g_att[tok * DMODEL + h * HD] = o;
        o.x = acc0[4] * r0; o.y = acc0[5] * r0; o.z = acc0[6] * r0; o.w = acc0[7] * r0;
        *(float4*)&g_att[tok * DMODEL + h * HD + 4] = o;
    }
    {
        int tok = bt * NSEQ + tid + 256;
        float4 o;
        o.x = acc1[0] * r1; o.y = acc1[1] * r1; o.z = acc1[2] * r1; o.w = acc1[3] * r1;
        *(float4*)&g_att[tok * DMODEL + h * HD] = o;
        o.x = acc1[4] * r1; o.y = acc1[5] * r1; o.z = acc1[6] * r1; o.w = acc1[7] * r1;
        *(float4*)&g_att[tok * DMODEL + h * HD + 4] = o;
    }
}

// ---------------------------------------------------------------------------
// Kernel 3: out = relu(att @ W10 + b10) @ W11 + b11.
// One row per thread; both weights in smem; h and y in registers.
// grid 384 x 128 threads.
// ---------------------------------------------------------------------------
__global__ __launch_bounds__(128) void proj_kernel(
    const float* __restrict__ W10, const float* __restrict__ b10,
    const float* __restrict__ W11, const float* __restrict__ b11,
    float* __restrict__ out)
{
    __shared__ float sW10[DMODEL * DMODEL];
    __shared__ float sW11[DMODEL * DMODEL];
    __shared__ float sb10[DMODEL];
    __shared__ float sb11[DMODEL];

    const int tid = threadIdx.x;
    for (int e = tid; e < DMODEL * DMODEL; e += 128) {
        sW10[e] = W10[e];
        sW11[e] = W11[e];
    }
    if (tid < DMODEL) { sb10[tid] = b10[tid]; sb11[tid] = b11[tid]; }
    __syncthreads();

    const int row = blockIdx.x * 128 + tid;
    const float4* x4 = (const float4*)(g_att + row * DMODEL);

    float hbuf[64];
    #pragma unroll
    for (int jj = 0; jj < 64; jj++) hbuf[jj] = sb10[jj];

    #pragma unroll 1
    for (int i4 = 0; i4 < 16; i4++) {
        float4 xv = x4[i4];
        const float4* w0 = (const float4*)&sW10[(i4 * 4 + 0) * 64];
        const float4* w1 = (const float4*)&sW10[(i4 * 4 + 1) * 64];
        const float4* w2 = (const float4*)&sW10[(i4 * 4 + 2) * 64];
        const float4* w3 = (const float4*)&sW10[(i4 * 4 + 3) * 64];
        #pragma unroll
        for (int jq = 0; jq < 16; jq++) {
            float4 wa = w0[jq];
            hbuf[4 * jq + 0] = __fmaf_rn(xv.x, wa.x, hbuf[4 * jq + 0]);
            hbuf[4 * jq + 1] = __fmaf_rn(xv.x, wa.y, hbuf[4 * jq + 1]);
            hbuf[4 * jq + 2] = __fmaf_rn(xv.x, wa.z, hbuf[4 * jq + 2]);
            hbuf[4 * jq + 3] = __fmaf_rn(xv.x, wa.w, hbuf[4 * jq + 3]);
            float4 wb = w1[jq];
            hbuf[4 * jq + 0] = __fmaf_rn(xv.y, wb.x, hbuf[4 * jq + 0]);
            hbuf[4 * jq + 1] = __fmaf_rn(xv.y, wb.y, hbuf[4 * jq + 1]);
            hbuf[4 * jq + 2] = __fmaf_rn(xv.y, wb.z, hbuf[4 * jq + 2]);
            hbuf[4 * jq + 3] = __fmaf_rn(xv.y, wb.w, hbuf[4 * jq + 3]);
            float4 wc = w2[jq];
            hbuf[4 * jq + 0] = __fmaf_rn(xv.z, wc.x, hbuf[4 * jq + 0]);
            hbuf[4 * jq + 1] = __fmaf_rn(xv.z, wc.y, hbuf[4 * jq + 1]);
            hbuf[4 * jq + 2] = __fmaf_rn(xv.z, wc.z, hbuf[4 * jq + 2]);
            hbuf[4 * jq + 3] = __fmaf_rn(xv.z, wc.w, hbuf[4 * jq + 3]);
            float4 wd = w3[jq];
            hbuf[4 * jq + 0] = __fmaf_rn(xv.w, wd.x, hbuf[4 * jq + 0]);
            hbuf[4 * jq + 1] = __fmaf_rn(xv.w, wd.y, hbuf[4 * jq + 1]);
            hbuf[4 * jq + 2] = __fmaf_rn(xv.w, wd.z, hbuf[4 * jq + 2]);
            hbuf[4 * jq + 3] = __fmaf_rn(xv.w, wd.w, hbuf[4 * jq + 3]);
        }
    }

    #pragma unroll
    for (int jj = 0; jj < 64; jj++) hbuf[jj] = fmaxf(hbuf[jj], 0.0f);

    float ybuf[64];
    #pragma unroll
    for (int jj = 0; jj < 64; jj++) ybuf[jj] = sb11[jj];

    #pragma unroll
    for (int i = 0; i < 64; i++) {
        float hv = hbuf[i];
        const float4* wr = (const float4*)&sW11[i * 64];
        #pragma unroll
        for (int jq = 0; jq < 16; jq++) {
            float4 w = wr[jq];
            ybuf[4 * jq + 0] = __fmaf_rn(hv, w.x, ybuf[4 * jq + 0]);
            ybuf[4 * jq + 1] = __fmaf_rn(hv, w.y, ybuf[4 * jq + 1]);
            ybuf[4 * jq + 2] = __fmaf_rn(hv, w.z, ybuf[4 * jq + 2]);
            ybuf[4 * jq + 3] = __fmaf_rn(hv, w.w, ybuf[4 * jq + 3]);
        }
    }

    float* orow = out + row * DMODEL;
    #pragma unroll
    for (int jq = 0; jq < 16; jq++) {
        float4 o;
        o.x = ybuf[4 * jq + 0];
        o.y = ybuf[4 * jq + 1];
        o.z = ybuf[4 * jq + 2];
        o.w = ybuf[4 * jq + 3];
        *(float4*)&orow[4 * jq] = o;
    }
}

// ---------------------------------------------------------------------------
extern "C" void kernel_launch(void* const* d_in, const int* in_sizes, int n_in,
                              void* d_out, int out_size)
{
    const float* X   = (const float*)d_in[0];
    const float* STE = (const float*)d_in[1];
    const float* W7  = (const float*)d_in[2];
    const float* b7  = (const float*)d_in[3];
    const float* W8  = (const float*)d_in[4];
    const float* b8  = (const float*)d_in[5];
    const float* W9  = (const float*)d_in[6];
    const float* b9  = (const float*)d_in[7];
    const float* W10 = (const float*)d_in[8];
    const float* b10 = (const float*)d_in[9];
    const float* W11 = (const float*)d_in[10];
    const float* b11 = (const float*)d_in[11];
    float* out = (float*)d_out;

    qkv_kernel<<<dim3(TOKENS / 64, 3), 256>>>(X, STE, W7, b7, W8, b8, W9, b9);
    attn_kernel<<<dim3(NBT, KH), 256>>>();
    proj_kernel<<<TOKENS / 128, 128>>>(W10, b10, W11, b11, out);
}